// round 1
// baseline (speedup 1.0000x reference)
#include <cuda_runtime.h>
#include <cuda_fp16.h>

// Problem constants
#define BATCH 256
#define NCAPS 1152
#define INC   8
#define KCAPS 10
#define OUTC  16

// u_hat scratch: [K, B, N, OUTC] in fp16 = 94.4 MB (fits in L2: 126 MB)
__device__ __half g_uhat[(size_t)KCAPS * BATCH * NCAPS * OUTC];

// ---------- packed fp32x2 helpers (sm_103a) ----------
__device__ __forceinline__ unsigned long long pack2(float x, float y) {
    unsigned long long r;
    asm("mov.b64 %0, {%1, %2};" : "=l"(r) : "f"(x), "f"(y));
    return r;
}
__device__ __forceinline__ unsigned long long fma2(unsigned long long a,
                                                   unsigned long long b,
                                                   unsigned long long c) {
    unsigned long long d;
    asm("fma.rn.f32x2 %0, %1, %2, %3;" : "=l"(d) : "l"(a), "l"(b), "l"(c));
    return d;
}
__device__ __forceinline__ float2 unpack2(unsigned long long v) {
    float2 f;
    asm("mov.b64 {%0, %1}, %2;" : "=f"(f.x), "=f"(f.y) : "l"(v));
    return f;
}

// =====================================================================
// Phase 1: u_hat[k,b,n,o] = sum_i u[b,n,i] * W[k,n,i,o], written as fp16.
// Grid: 144 CTAs, one per 8-wide n-tile. 640 threads.
// Thread = (k, n_local, o_quarter) x (b parity). W held in registers
// (8 i x 4 o = 16 packed f32x2 pairs), u duplicated-packed in smem so the
// scalar-broadcast operand is loaded as a ready-made f32x2.
// =====================================================================
__global__ __launch_bounds__(640, 1)
void uhat_kernel(const float* __restrict__ u, const float* __restrict__ W) {
    extern __shared__ float2 udup[];   // [256 b][64 r]  (r = nl*8 + i), value (u,u)
    const int n0 = blockIdx.x * 8;
    const int tid = threadIdx.x;

    // Stage u tile for ALL b into smem, duplicated: 256*64*8B = 128 KB
    for (int idx = tid; idx < BATCH * 64; idx += 640) {
        const int b = idx >> 6, r = idx & 63;
        const float v = u[b * (NCAPS * INC) + n0 * INC + r];
        udup[idx] = make_float2(v, v);
    }

    // Thread mapping
    const int oq = tid & 3;            // o quarter: o = oq*4 .. oq*4+3
    const int nl = (tid >> 2) & 7;     // n within tile
    int kk = tid >> 5;                 // 0..19
    int bsub = 0;
    if (kk >= KCAPS) { kk -= KCAPS; bsub = 1; }

    // Load W[k, n0+nl, 0..7, oq*4..+4] into registers, pre-packed as f32x2
    const float* wptr = W + (((kk * NCAPS) + n0 + nl) * INC) * OUTC + oq * 4;
    unsigned long long wp[8][2];
#pragma unroll
    for (int i = 0; i < 8; i++) {
        const float4 w4 = *reinterpret_cast<const float4*>(wptr + i * OUTC);
        wp[i][0] = pack2(w4.x, w4.y);
        wp[i][1] = pack2(w4.z, w4.w);
    }
    __syncthreads();

    const int n = n0 + nl;
    __half* dst_base = g_uhat + (size_t)(kk * BATCH) * NCAPS * OUTC
                              + (size_t)n * OUTC + oq * 4;

    for (int b = bsub; b < BATCH; b += 2) {
        const ulonglong2* up =
            reinterpret_cast<const ulonglong2*>(udup + b * 64 + nl * 8);
        unsigned long long acc0 = 0ull, acc1 = 0ull;  // (0.f,0.f)
#pragma unroll
        for (int i2 = 0; i2 < 4; i2++) {
            const ulonglong2 uu = up[i2];  // (u_{2i},u_{2i}), (u_{2i+1},u_{2i+1})
            acc0 = fma2(uu.x, wp[2 * i2][0], acc0);
            acc1 = fma2(uu.x, wp[2 * i2][1], acc1);
            acc0 = fma2(uu.y, wp[2 * i2 + 1][0], acc0);
            acc1 = fma2(uu.y, wp[2 * i2 + 1][1], acc1);
        }
        const float2 a0 = unpack2(acc0);
        const float2 a1 = unpack2(acc1);
        union { uint2 u32x2; __half2 h[2]; } cv;
        cv.h[0] = __floats2half2_rn(a0.x, a0.y);
        cv.h[1] = __floats2half2_rn(a1.x, a1.y);
        *reinterpret_cast<uint2*>(dst_base + (size_t)b * NCAPS * OUTC) = cv.u32x2;
    }
}

// =====================================================================
// Phase 2: full dynamic routing for one (k,b) per CTA. 256 threads.
// u_hat slice (1152x16) staged fp32 in smem with stride-17 padding
// (odd stride -> conflict-free column reads). b_ij is a scalar per n.
// =====================================================================
#define STR 17
#define SMEM2_FLOATS (NCAPS * STR + NCAPS + NCAPS + 128 + 16 + 8)

__global__ __launch_bounds__(256)
void routing_kernel(float* __restrict__ out) {
    extern __shared__ float sm[];
    float* uh  = sm;                    // [1152 * 17]
    float* bb  = uh + NCAPS * STR;      // [1152] routing logits
    float* ee  = bb + NCAPS;            // [1152] exp weights
    float* red = ee + NCAPS;            // [128] reduce scratch
    float* sv  = red + 128;             // [16]  current v_j
    float* sc  = sv + 16;               // scalars: [0]=max, [1]=1/Z

    const int tid = threadIdx.x;
    const int b = blockIdx.x, k = blockIdx.y;
    const __half* src = g_uhat + ((size_t)(k * BATCH + b)) * NCAPS * OUTC;

    // Load + convert u_hat slice (fp16 -> fp32 smem)
    for (int m = tid; m < NCAPS * 2; m += 256) {
        const uint4 pkt = *reinterpret_cast<const uint4*>(src + m * 8);
        const __half2* hp = reinterpret_cast<const __half2*>(&pkt);
        const int n = m >> 1, h = (m & 1) * 8;
        float* dstp = uh + n * STR + h;
#pragma unroll
        for (int j = 0; j < 4; j++) {
            const float2 f = __half22float2(hp[j]);
            dstp[2 * j] = f.x;
            dstp[2 * j + 1] = f.y;
        }
    }
    for (int n = tid; n < NCAPS; n += 256) bb[n] = 0.f;
    __syncthreads();

    const int o = tid & 15, g = tid >> 4;      // column / n-slice
    const int lane = tid & 31, warp = tid >> 5;

    // ---- iteration 1: uniform coefficients -> s = mean_n u_hat ----
    {
        float p = 0.f;
#pragma unroll 4
        for (int j = 0; j < 72; j++) p += uh[(g + 16 * j) * STR + o];
        p += __shfl_xor_sync(0xffffffffu, p, 16);
        if (lane < 16) red[warp * 16 + o] = p;
        __syncthreads();
        if (tid < 16) {
            float s = 0.f;
#pragma unroll
            for (int w = 0; w < 8; w++) s += red[w * 16 + tid];
            s *= (1.f / (float)NCAPS);
            float q = s * s;
            q += __shfl_xor_sync(0xffffu, q, 8);
            q += __shfl_xor_sync(0xffffu, q, 4);
            q += __shfl_xor_sync(0xffffu, q, 2);
            q += __shfl_xor_sync(0xffffu, q, 1);
            sv[tid] = s * (q / ((1.f + q) * sqrtf(q)));
        }
        __syncthreads();
    }

    // ---- iterations 2 and 3 ----
    for (int it = 0; it < 2; it++) {
        // a[n] = <u_hat[n,:], v>, accumulate logits, track max
        float mloc = -3.0e38f;
        for (int n = tid; n < NCAPS; n += 256) {
            const float* row = uh + n * STR;
            float a = 0.f;
#pragma unroll
            for (int oo = 0; oo < OUTC; oo++) a = fmaf(row[oo], sv[oo], a);
            const float bn = bb[n] + a;
            bb[n] = bn;
            mloc = fmaxf(mloc, bn);
        }
#pragma unroll
        for (int off = 16; off; off >>= 1)
            mloc = fmaxf(mloc, __shfl_xor_sync(0xffffffffu, mloc, off));
        if (lane == 0) red[warp] = mloc;
        __syncthreads();
        if (tid == 0) {
            float m = red[0];
#pragma unroll
            for (int w = 1; w < 8; w++) m = fmaxf(m, red[w]);
            sc[0] = m;
        }
        __syncthreads();

        // e[n] = exp(b[n] - max), Z = sum e
        const float mx = sc[0];
        float zloc = 0.f;
        for (int n = tid; n < NCAPS; n += 256) {
            const float e = __expf(bb[n] - mx);
            ee[n] = e;
            zloc += e;
        }
#pragma unroll
        for (int off = 16; off; off >>= 1)
            zloc += __shfl_xor_sync(0xffffffffu, zloc, off);
        if (lane == 0) red[warp] = zloc;
        __syncthreads();
        if (tid == 0) {
            float z = 0.f;
#pragma unroll
            for (int w = 0; w < 8; w++) z += red[w];
            sc[1] = 1.f / z;
        }
        __syncthreads();

        // s[o] = (1/Z) * sum_n e[n] * u_hat[n,o], then squash
        float pp = 0.f;
#pragma unroll 4
        for (int j = 0; j < 72; j++) {
            const int n = g + 16 * j;
            pp = fmaf(ee[n], uh[n * STR + o], pp);
        }
        pp += __shfl_xor_sync(0xffffffffu, pp, 16);
        if (lane < 16) red[warp * 16 + o] = pp;
        __syncthreads();
        if (tid < 16) {
            float s = 0.f;
#pragma unroll
            for (int w = 0; w < 8; w++) s += red[w * 16 + tid];
            s *= sc[1];
            float q = s * s;
            q += __shfl_xor_sync(0xffffu, q, 8);
            q += __shfl_xor_sync(0xffffu, q, 4);
            q += __shfl_xor_sync(0xffffu, q, 2);
            q += __shfl_xor_sync(0xffffu, q, 1);
            sv[tid] = s * (q / ((1.f + q) * sqrtf(q)));
        }
        __syncthreads();
    }

    if (tid < 16) out[((size_t)(k * BATCH) + b) * OUTC + tid] = sv[tid];
}

extern "C" void kernel_launch(void* const* d_in, const int* in_sizes, int n_in,
                              void* d_out, int out_size) {
    const float* u = (const float*)d_in[0];   // [256, 1152, 8]
    const float* W = (const float*)d_in[1];   // [10, 1152, 8, 16]
    float* out = (float*)d_out;               // [10, 256, 1, 1, 16]

    const int smem1 = BATCH * 64 * sizeof(float2);       // 131072 B
    const int smem2 = SMEM2_FLOATS * sizeof(float);      // 88160 B
    cudaFuncSetAttribute(uhat_kernel,
                         cudaFuncAttributeMaxDynamicSharedMemorySize, smem1);
    cudaFuncSetAttribute(routing_kernel,
                         cudaFuncAttributeMaxDynamicSharedMemorySize, smem2);

    uhat_kernel<<<NCAPS / 8, 640, smem1>>>(u, W);
    routing_kernel<<<dim3(BATCH, KCAPS), 256, smem2>>>(out);
}

// round 6
// speedup vs baseline: 2.6589x; 2.6589x over previous
#include <cuda_runtime.h>
#include <cuda_fp16.h>

// Problem constants
#define BATCH 256
#define NCAPS 1152
#define INC   8
#define KCAPS 10
#define OUTC  16

// u_hat scratch: [K, B, N, OUTC] fp16 = 94.4 MB (mostly L2-resident: 126 MB L2)
__device__ __align__(16) __half g_uhat[(size_t)KCAPS * BATCH * NCAPS * OUTC];

// ---------- packed fp32x2 helpers (sm_103a) ----------
__device__ __forceinline__ unsigned long long pack2(float x, float y) {
    unsigned long long r;
    asm("mov.b64 %0, {%1, %2};" : "=l"(r) : "f"(x), "f"(y));
    return r;
}
__device__ __forceinline__ unsigned long long fma2(unsigned long long a,
                                                   unsigned long long b,
                                                   unsigned long long c) {
    unsigned long long d;
    asm("fma.rn.f32x2 %0, %1, %2, %3;" : "=l"(d) : "l"(a), "l"(b), "l"(c));
    return d;
}
__device__ __forceinline__ unsigned long long add2(unsigned long long a,
                                                   unsigned long long b) {
    unsigned long long d;
    asm("add.rn.f32x2 %0, %1, %2;" : "=l"(d) : "l"(a), "l"(b));
    return d;
}
__device__ __forceinline__ float2 unpack2(unsigned long long v) {
    float2 f;
    asm("mov.b64 {%0, %1}, %2;" : "=f"(f.x), "=f"(f.y) : "l"(v));
    return f;
}

// =====================================================================
// Phase 1: u_hat[k,b,n,o] = sum_i u[b,n,i]*W[k,n,i,o] -> fp16.
// Grid 288 (n-tiles of 4), 320 threads, 64KB smem -> 2 CTAs/SM (40 warps).
// W in registers (8i x 4o packed f32x2); u duplicated-packed in smem.
// =====================================================================
__global__ __launch_bounds__(320)
void uhat_kernel(const float* __restrict__ u, const float* __restrict__ W) {
    extern __shared__ float2 udup[];   // [256 b][32 r]  (r = nl*8 + i), value (u,u)
    const int n0 = blockIdx.x * 4;
    const int tid = threadIdx.x;

    // Stage u tile for ALL b into smem, duplicated: 256*32*8B = 64 KB
    for (int idx = tid; idx < BATCH * 32; idx += 320) {
        const int b = idx >> 5, r = idx & 31;
        const float v = u[b * (NCAPS * INC) + n0 * INC + r];
        udup[idx] = make_float2(v, v);
    }

    // Thread mapping: 4 oq x 4 nl x 10 k x 2 bsub = 320
    const int oq = tid & 3;            // o quarter
    const int nl = (tid >> 2) & 3;     // n within tile
    int kk = tid >> 4;                 // 0..19
    int bsub = 0;
    if (kk >= KCAPS) { kk -= KCAPS; bsub = 1; }

    const float* wptr = W + (((kk * NCAPS) + n0 + nl) * INC) * OUTC + oq * 4;
    unsigned long long wp[8][2];
#pragma unroll
    for (int i = 0; i < 8; i++) {
        const float4 w4 = *reinterpret_cast<const float4*>(wptr + i * OUTC);
        wp[i][0] = pack2(w4.x, w4.y);
        wp[i][1] = pack2(w4.z, w4.w);
    }
    __syncthreads();

    const int n = n0 + nl;
    __half* dst_base = g_uhat + (size_t)(kk * BATCH) * NCAPS * OUTC
                              + (size_t)n * OUTC + oq * 4;

    for (int b = bsub; b < BATCH; b += 2) {
        const ulonglong2* up =
            reinterpret_cast<const ulonglong2*>(udup + b * 32 + nl * 8);
        unsigned long long acc0 = 0ull, acc1 = 0ull;
#pragma unroll
        for (int i2 = 0; i2 < 4; i2++) {
            const ulonglong2 uu = up[i2];
            acc0 = fma2(uu.x, wp[2 * i2][0], acc0);
            acc1 = fma2(uu.x, wp[2 * i2][1], acc1);
            acc0 = fma2(uu.y, wp[2 * i2 + 1][0], acc0);
            acc1 = fma2(uu.y, wp[2 * i2 + 1][1], acc1);
        }
        const float2 a0 = unpack2(acc0);
        const float2 a1 = unpack2(acc1);
        union { uint2 u32x2; __half2 h[2]; } cv;
        cv.h[0] = __floats2half2_rn(a0.x, a0.y);
        cv.h[1] = __floats2half2_rn(a1.x, a1.y);
        *reinterpret_cast<uint2*>(dst_base + (size_t)b * NCAPS * OUTC) = cv.u32x2;
    }
}

// =====================================================================
// Phase 2: routing for one (k,b) per CTA. 288 threads, u_hat in REGISTERS:
// thread owns rows {t, t+288, t+576, t+864}, 16 cols as 8 packed f32x2.
// smem only for reductions (~26 KB) -> 2 CTAs/SM.
// =====================================================================
#define RT   288
#define RPT  4
#define SPAD 20   // floats per scratch row (16B-aligned, STS.128-friendly)

__global__ __launch_bounds__(RT, 2)
void routing_kernel(float* __restrict__ out) {
    __shared__ __align__(16) float sred[RT * SPAD];   // per-thread s partials
    __shared__ __align__(16) float sB[36 * 16];       // stage-A partials
    __shared__ float swm[9];                          // per-warp max
    __shared__ float swz[9];                          // per-warp Z partial
    __shared__ __align__(16) float sv[16];            // current v_j

    const int tid = threadIdx.x;
    const int lane = tid & 31, warp = tid >> 5;
    const int b = blockIdx.x, k = blockIdx.y;
    const __half* src = g_uhat + ((size_t)(k * BATCH + b)) * NCAPS * OUTC;

    // Load 4 rows x 16 fp16 -> 8 packed f32x2 each
    unsigned long long uh[RPT][8];
#pragma unroll
    for (int j = 0; j < RPT; j++) {
        const int n = tid + RT * j;
        const uint4* p = reinterpret_cast<const uint4*>(src + n * OUTC);
        union { uint4 q; __half2 h[4]; } w0, w1;
        w0.q = p[0];
        w1.q = p[1];
#pragma unroll
        for (int c = 0; c < 4; c++) {
            const float2 f0 = __half22float2(w0.h[c]);
            uh[j][c] = pack2(f0.x, f0.y);
            const float2 f1 = __half22float2(w1.h[c]);
            uh[j][4 + c] = pack2(f1.x, f1.y);
        }
    }

    float bl[RPT];
#pragma unroll
    for (int j = 0; j < RPT; j++) bl[j] = 0.f;

    float* myrow = sred + tid * SPAD;

    // ---- iteration 1: uniform coefficients -> s = mean_n u_hat ----
    {
        unsigned long long sp[8];
#pragma unroll
        for (int c = 0; c < 8; c++) sp[c] = uh[0][c];
#pragma unroll
        for (int j = 1; j < RPT; j++)
#pragma unroll
            for (int c = 0; c < 8; c++) sp[c] = add2(sp[c], uh[j][c]);
#pragma unroll
        for (int c = 0; c < 8; c++)
            reinterpret_cast<unsigned long long*>(myrow)[c] = sp[c];
    }
    __syncthreads();
    {   // stage A: 36 groups x 8 packed cols, each sums 8 scratch rows
        const int o2 = tid & 7, grp = tid >> 3;
        unsigned long long acc = 0ull;
#pragma unroll
        for (int rr = 0; rr < 8; rr++)
            acc = add2(acc, reinterpret_cast<const unsigned long long*>(
                                sred + (grp * 8 + rr) * SPAD)[o2]);
        reinterpret_cast<unsigned long long*>(sB)[grp * 8 + o2] = acc;
    }
    __syncthreads();
    if (tid < 16) {   // stage B + squash
        float s = 0.f;
#pragma unroll
        for (int g = 0; g < 36; g++) s += sB[g * 16 + tid];
        s *= (1.f / (float)NCAPS);
        float q = s * s;
        q += __shfl_xor_sync(0xffffu, q, 8);
        q += __shfl_xor_sync(0xffffu, q, 4);
        q += __shfl_xor_sync(0xffffu, q, 2);
        q += __shfl_xor_sync(0xffffu, q, 1);
        sv[tid] = s * (q / ((1.f + q) * sqrtf(q)));
    }
    __syncthreads();

    // ---- iterations 2 and 3 ----
    for (int it = 0; it < 2; it++) {
        // a[n] = <u_hat[n,:], v>; update logits; warp max
        unsigned long long vp[8];
#pragma unroll
        for (int c = 0; c < 8; c++)
            vp[c] = reinterpret_cast<const unsigned long long*>(sv)[c];
        float mloc = -3.0e38f;
#pragma unroll
        for (int j = 0; j < RPT; j++) {
            unsigned long long ap = 0ull;
#pragma unroll
            for (int c = 0; c < 8; c++) ap = fma2(uh[j][c], vp[c], ap);
            const float2 af = unpack2(ap);
            bl[j] += af.x + af.y;
            mloc = fmaxf(mloc, bl[j]);
        }
#pragma unroll
        for (int off = 16; off; off >>= 1)
            mloc = fmaxf(mloc, __shfl_xor_sync(0xffffffffu, mloc, off));
        if (lane == 0) swm[warp] = mloc;
        __syncthreads();

        // global max (every thread reads 9 values), exp, warp Z
        float mx = swm[0];
#pragma unroll
        for (int w = 1; w < 9; w++) mx = fmaxf(mx, swm[w]);
        float el[RPT];
        float zloc = 0.f;
#pragma unroll
        for (int j = 0; j < RPT; j++) {
            el[j] = __expf(bl[j] - mx);
            zloc += el[j];
        }
#pragma unroll
        for (int off = 16; off; off >>= 1)
            zloc += __shfl_xor_sync(0xffffffffu, zloc, off);
        if (lane == 0) swz[warp] = zloc;

        // s partials (independent of Z; scale applied in stage B)
        unsigned long long sp[8];
#pragma unroll
        for (int c = 0; c < 8; c++) sp[c] = 0ull;
#pragma unroll
        for (int j = 0; j < RPT; j++) {
            const unsigned long long e2 = pack2(el[j], el[j]);
#pragma unroll
            for (int c = 0; c < 8; c++) sp[c] = fma2(e2, uh[j][c], sp[c]);
        }
#pragma unroll
        for (int c = 0; c < 8; c++)
            reinterpret_cast<unsigned long long*>(myrow)[c] = sp[c];
        __syncthreads();

        {   // stage A
            const int o2 = tid & 7, grp = tid >> 3;
            unsigned long long acc = 0ull;
#pragma unroll
            for (int rr = 0; rr < 8; rr++)
                acc = add2(acc, reinterpret_cast<const unsigned long long*>(
                                    sred + (grp * 8 + rr) * SPAD)[o2]);
            reinterpret_cast<unsigned long long*>(sB)[grp * 8 + o2] = acc;
        }
        __syncthreads();

        if (tid < 16) {   // stage B: finish Z, s, squash
            float z = swz[0];
#pragma unroll
            for (int w = 1; w < 9; w++) z += swz[w];
            float s = 0.f;
#pragma unroll
            for (int g = 0; g < 36; g++) s += sB[g * 16 + tid];
            s *= (1.f / z);
            float q = s * s;
            q += __shfl_xor_sync(0xffffu, q, 8);
            q += __shfl_xor_sync(0xffffu, q, 4);
            q += __shfl_xor_sync(0xffffu, q, 2);
            q += __shfl_xor_sync(0xffffu, q, 1);
            const float v = s * (q / ((1.f + q) * sqrtf(q)));
            sv[tid] = v;
            if (it == 1)
                out[((size_t)(k * BATCH) + b) * OUTC + tid] = v;
        }
        __syncthreads();
    }
}

extern "C" void kernel_launch(void* const* d_in, const int* in_sizes, int n_in,
                              void* d_out, int out_size) {
    const float* u = (const float*)d_in[0];   // [256, 1152, 8]
    const float* W = (const float*)d_in[1];   // [10, 1152, 8, 16]
    float* out = (float*)d_out;               // [10, 256, 1, 1, 16]

    const int smem1 = BATCH * 32 * sizeof(float2);   // 65536 B
    cudaFuncSetAttribute(uhat_kernel,
                         cudaFuncAttributeMaxDynamicSharedMemorySize, smem1);

    uhat_kernel<<<NCAPS / 4, 320, smem1>>>(u, W);
    routing_kernel<<<dim3(BATCH, KCAPS), RT>>>(out);
}